// round 2
// baseline (speedup 1.0000x reference)
#include <cuda_runtime.h>
#include <cuda_bf16.h>

#define TPAD   192
#define CCH    80
#define NSEG   7
#define SGRID  64
#define MINSEG 19
#define NVEC   20              // float4 per row
#define ROWV   (TPAD * NVEC)   // 3840 float4 per batch
#define BMAX   4096

// Packed per-row plan: .x = lam, .y = __int_as_float(src)  (src = -1 => zero row)
__device__ float2 g_tab[BMAX * TPAD];

__global__ __launch_bounds__(512)
void plan_kernel(const int*   __restrict__ len_seq,
                 const float* __restrict__ scales,
                 const int*   __restrict__ len_seg_raw)
{
    const int b   = blockIdx.x;
    const int tid = threadIdx.x;

    __shared__ float s_scale[NSEG];
    __shared__ int   s_lenseg[NSEG];
    __shared__ int   s_off[NSEG];
    __shared__ int   s_cnt[NSEG];
    __shared__ int   s_base[NSEG];
    __shared__ int   s_wcnt[14];       // 14 warps cover 448 slots
    __shared__ int   s_total;
    __shared__ int   s_src[TPAD];
    __shared__ float s_lam[TPAD];

    if (tid < NSEG) {
        s_scale[tid]  = scales[b * NSEG + tid] + 0.5f;
        s_lenseg[tid] = len_seg_raw[b * NSEG + tid] + MINSEG;
    }
    __syncthreads();

    if (tid == 0) {
        int acc = 0;
        #pragma unroll
        for (int s = 0; s < NSEG; s++) { s_off[s] = acc; acc += s_lenseg[s]; }
    }
    __syncthreads();

    // Parallel mask evaluation: slot (s,i) for tid < 448; count via ballot.
    // Mask terms are integer comparisons on exactly-representable floats.
    if (tid < NSEG * SGRID) {
        const int s = tid >> 6;
        const int i = tid & 63;
        const int lim = min(s_lenseg[s] - 1, len_seq[b] - 1 - s_off[s]);
        const float v = __fdiv_rn((float)i, s_scale[s]);   // IEEE RN, matches JAX
        const bool m = (lim > 0) && (floorf(v) < (float)lim);
        const unsigned bal = __ballot_sync(0xffffffffu, m);
        if ((tid & 31) == 0) s_wcnt[tid >> 5] = __popc(bal);
    }
    __syncthreads();

    if (tid == 0) {
        int acc = 0;
        #pragma unroll
        for (int s = 0; s < NSEG; s++) {
            const int cnt = s_wcnt[2 * s] + s_wcnt[2 * s + 1];
            s_base[s] = acc; s_cnt[s] = cnt; acc += cnt;
        }
        s_total = min(acc, TPAD);      // rows with pos >= 192 dropped by reference
    }
    __syncthreads();

    // Fill compact table (masked slots of a segment are a prefix of i).
    if (tid < NSEG * SGRID) {
        const int s = tid >> 6;
        const int i = tid & 63;
        if (i < s_cnt[s]) {
            const int p = s_base[s] + i;
            if (p < TPAD) {
                const float v  = __fdiv_rn((float)i, s_scale[s]);
                const float fl = floorf(v);
                s_src[p] = min((int)fl + s_off[s], TPAD - 2);
                s_lam[p] = v - fl;
            }
        }
    }
    __syncthreads();

    if (tid < TPAD) {
        float2 t;
        if (tid < s_total) { t.x = s_lam[tid]; t.y = __int_as_float(s_src[tid]); }
        else               { t.x = 0.0f;      t.y = __int_as_float(-1); }
        g_tab[b * TPAD + tid] = t;
    }
}

__global__ __launch_bounds__(256)
void stream_kernel(const float* __restrict__ x,
                   float*       __restrict__ out,
                   int n4)
{
    const int g = blockIdx.x * 256 + threadIdx.x;
    if (g >= n4) return;

    const int b   = g / ROWV;
    const int e   = g - b * ROWV;
    const int row = e / NVEC;
    const int q   = e - row * NVEC;

    const float2 t   = g_tab[b * TPAD + row];
    const int    src = __float_as_int(t.y);

    float4 r = make_float4(0.f, 0.f, 0.f, 0.f);
    if (src >= 0) {
        const float4* __restrict__ xb =
            (const float4*)(x + (size_t)b * TPAD * CCH);
        const float4 a = __ldg(&xb[src * NVEC + q]);
        const float4 c = __ldg(&xb[(src + 1) * NVEC + q]);
        const float lam = t.x;
        r.x = fmaf(lam, c.x - a.x, a.x);
        r.y = fmaf(lam, c.y - a.y, a.y);
        r.z = fmaf(lam, c.z - a.z, a.z);
        r.w = fmaf(lam, c.w - a.w, a.w);
    }
    __stcs(((float4*)out) + g, r);   // streaming store: output never re-read
}

extern "C" void kernel_launch(void* const* d_in, const int* in_sizes, int n_in,
                              void* d_out, int out_size)
{
    const float* x           = (const float*)d_in[0];
    const int*   len_seq     = (const int*)  d_in[1];
    const float* scales      = (const float*)d_in[2];
    const int*   len_seg_raw = (const int*)  d_in[3];
    float*       out         = (float*)d_out;

    const int B  = in_sizes[1];
    const int n4 = B * ROWV;

    plan_kernel<<<B, 512>>>(len_seq, scales, len_seg_raw);
    stream_kernel<<<(n4 + 255) / 256, 256>>>(x, out, n4);
}

// round 3
// speedup vs baseline: 1.2114x; 1.2114x over previous
#include <cuda_runtime.h>
#include <cuda_bf16.h>

#define TPAD   192
#define CCH    80
#define NSEG   7
#define SGRID  64
#define MINSEG 19
#define NVEC   20              // float4 per row
#define ROWV   (TPAD * NVEC)   // 3840 float4 per batch

__global__ __launch_bounds__(512, 2)
void interp_lnr_kernel(const float* __restrict__ x,
                       const int*   __restrict__ len_seq,
                       const float* __restrict__ scales,
                       const int*   __restrict__ len_seg_raw,
                       float*       __restrict__ out)
{
    const int b   = blockIdx.x;
    const int tid = threadIdx.x;

    __shared__ float s_scale[NSEG];
    __shared__ int   s_lenseg[NSEG];
    __shared__ int   s_off[NSEG];
    __shared__ int   s_cnt[NSEG];
    __shared__ int   s_base[NSEG];
    __shared__ int   s_wcnt[14];       // 14 warps cover 448 slots
    __shared__ int   s_src[TPAD];
    __shared__ float s_lam[TPAD];

    // Pre-fill: pad rows get src = -1, lam = 0 (overwritten for live rows).
    if (tid < TPAD) { s_src[tid] = -1; s_lam[tid] = 0.0f; }

    if (tid < NSEG) {
        s_scale[tid]  = scales[b * NSEG + tid] + 0.5f;
        s_lenseg[tid] = len_seg_raw[b * NSEG + tid] + MINSEG;
    }
    __syncthreads();

    if (tid == 0) {
        int acc = 0;
        #pragma unroll
        for (int s = 0; s < NSEG; s++) { s_off[s] = acc; acc += s_lenseg[s]; }
    }
    __syncthreads();

    // Parallel mask evaluation: slot (s,i) for tid < 448; count via ballot.
    // Both mask terms are integer comparisons on exactly-representable floats.
    if (tid < NSEG * SGRID) {
        const int s = tid >> 6;
        const int i = tid & 63;
        const int lim = min(s_lenseg[s] - 1, len_seq[b] - 1 - s_off[s]);
        const float v = __fdiv_rn((float)i, s_scale[s]);   // IEEE RN, matches JAX
        const bool m = (lim > 0) && (floorf(v) < (float)lim);
        const unsigned bal = __ballot_sync(0xffffffffu, m);
        if ((tid & 31) == 0) s_wcnt[tid >> 5] = __popc(bal);
    }
    __syncthreads();

    if (tid == 0) {
        int acc = 0;
        #pragma unroll
        for (int s = 0; s < NSEG; s++) {
            const int cnt = s_wcnt[2 * s] + s_wcnt[2 * s + 1];
            s_base[s] = acc; s_cnt[s] = cnt; acc += cnt;
        }
    }
    __syncthreads();

    // Fill compact table (masked slots of a segment are a prefix of i).
    if (tid < NSEG * SGRID) {
        const int s = tid >> 6;
        const int i = tid & 63;
        if (i < s_cnt[s]) {
            const int p = s_base[s] + i;
            if (p < TPAD) {                      // pos >= 192 dropped by reference
                const float v  = __fdiv_rn((float)i, s_scale[s]);
                const float fl = floorf(v);
                s_src[p] = min((int)fl + s_off[s], TPAD - 2);
                s_lam[p] = v - fl;
            }
        }
    }
    __syncthreads();

    const float4* __restrict__ xb = (const float4*)(x   + (size_t)b * TPAD * CCH);
    float4*       __restrict__ ob = (float4*)      (out + (size_t)b * TPAD * CCH);

    // Stream 3840 float4: 2 macro-iterations x 4 slots, loads batched for MLP.
    #pragma unroll 1
    for (int base = 0; base < ROWV; base += 4 * 512) {
        float4 A[4], Cv[4];
        float  lam[4];
        int    src[4];

        #pragma unroll
        for (int k = 0; k < 4; k++) {
            const int e   = base + tid + k * 512;
            const int ec  = min(e, ROWV - 1);
            const int row = ec / NVEC;
            const int q   = ec - row * NVEC;
            src[k] = s_src[row];
            lam[k] = s_lam[row];
            if (src[k] >= 0) {
                A[k]  = xb[src[k] * NVEC + q];
                Cv[k] = xb[src[k] * NVEC + NVEC + q];
            }
        }

        #pragma unroll
        for (int k = 0; k < 4; k++) {
            const int e = base + tid + k * 512;
            if (e < ROWV) {
                float4 r = make_float4(0.f, 0.f, 0.f, 0.f);
                if (src[k] >= 0) {
                    const float l = lam[k];
                    r.x = fmaf(l, Cv[k].x - A[k].x, A[k].x);
                    r.y = fmaf(l, Cv[k].y - A[k].y, A[k].y);
                    r.z = fmaf(l, Cv[k].z - A[k].z, A[k].z);
                    r.w = fmaf(l, Cv[k].w - A[k].w, A[k].w);
                }
                ob[e] = r;
            }
        }
    }
}

extern "C" void kernel_launch(void* const* d_in, const int* in_sizes, int n_in,
                              void* d_out, int out_size)
{
    const float* x           = (const float*)d_in[0];
    const int*   len_seq     = (const int*)  d_in[1];
    const float* scales      = (const float*)d_in[2];
    const int*   len_seg_raw = (const int*)  d_in[3];
    float*       out         = (float*)d_out;

    const int B = in_sizes[1];
    interp_lnr_kernel<<<B, 512>>>(x, len_seq, scales, len_seg_raw, out);
}

// round 5
// speedup vs baseline: 1.4305x; 1.1809x over previous
#include <cuda_runtime.h>
#include <cuda_bf16.h>

#define TPAD   192
#define CCH    80
#define NSEG   7
#define SGRID  64
#define MINSEG 19
#define NV8    10              // 32-byte chunks per row (80 floats = 10 x 8)
#define ROWV8  (TPAD * NV8)    // 1920 chunks per batch

// x is read-only and re-read across graph replays: keep it in L2.
// sm_103: eviction hints require 256-bit (.v4.b64) accesses.
__device__ __forceinline__ ulonglong4 ldg256_evict_last(const ulonglong4* p) {
    ulonglong4 v;
    asm volatile("ld.global.nc.L2::evict_last.v4.b64 {%0,%1,%2,%3}, [%4];"
                 : "=l"(v.x), "=l"(v.y), "=l"(v.z), "=l"(v.w) : "l"(p));
    return v;
}
// out is write-once, never re-read: don't let it pollute L2.
__device__ __forceinline__ void stg256_evict_first(ulonglong4* p, ulonglong4 v) {
    asm volatile("st.global.L2::evict_first.v4.b64 [%0], {%1,%2,%3,%4};"
                 :: "l"(p), "l"(v.x), "l"(v.y), "l"(v.z), "l"(v.w) : "memory");
}

__device__ __forceinline__ float2 u2f2(unsigned long long u) {
    float2 f;
    f.x = __uint_as_float((unsigned)(u & 0xffffffffull));
    f.y = __uint_as_float((unsigned)(u >> 32));
    return f;
}
__device__ __forceinline__ unsigned long long f22u(float2 f) {
    return (unsigned long long)__float_as_uint(f.x)
         | ((unsigned long long)__float_as_uint(f.y) << 32);
}
__device__ __forceinline__ unsigned long long lerp64(unsigned long long ua,
                                                     unsigned long long uc,
                                                     float lam) {
    const float2 a = u2f2(ua), c = u2f2(uc);
    float2 r;
    r.x = fmaf(lam, c.x - a.x, a.x);
    r.y = fmaf(lam, c.y - a.y, a.y);
    return f22u(r);
}

__global__ __launch_bounds__(512)
void interp_lnr_kernel(const float* __restrict__ x,
                       const int*   __restrict__ len_seq,
                       const float* __restrict__ scales,
                       const int*   __restrict__ len_seg_raw,
                       float*       __restrict__ out)
{
    const int b   = blockIdx.x;
    const int tid = threadIdx.x;

    __shared__ float s_scale[NSEG];
    __shared__ int   s_lenseg[NSEG];
    __shared__ int   s_off[NSEG];
    __shared__ int   s_cnt[NSEG];
    __shared__ int   s_base[NSEG];
    __shared__ int   s_wcnt[14];       // 14 warps cover 448 slots
    __shared__ int   s_src[TPAD];
    __shared__ float s_lam[TPAD];

    // Pre-fill: pad rows get src = -1, lam = 0 (overwritten for live rows).
    if (tid < TPAD) { s_src[tid] = -1; s_lam[tid] = 0.0f; }

    if (tid < NSEG) {
        s_scale[tid]  = scales[b * NSEG + tid] + 0.5f;
        s_lenseg[tid] = len_seg_raw[b * NSEG + tid] + MINSEG;
    }
    __syncthreads();

    if (tid == 0) {
        int acc = 0;
        #pragma unroll
        for (int s = 0; s < NSEG; s++) { s_off[s] = acc; acc += s_lenseg[s]; }
    }
    __syncthreads();

    // Parallel mask evaluation: slot (s,i) for tid < 448; count via ballot.
    // Both mask terms are integer comparisons on exactly-representable floats.
    if (tid < NSEG * SGRID) {
        const int s = tid >> 6;
        const int i = tid & 63;
        const int lim = min(s_lenseg[s] - 1, len_seq[b] - 1 - s_off[s]);
        const float v = __fdiv_rn((float)i, s_scale[s]);   // IEEE RN, matches JAX
        const bool m = (lim > 0) && (floorf(v) < (float)lim);
        const unsigned bal = __ballot_sync(0xffffffffu, m);
        if ((tid & 31) == 0) s_wcnt[tid >> 5] = __popc(bal);
    }
    __syncthreads();

    if (tid == 0) {
        int acc = 0;
        #pragma unroll
        for (int s = 0; s < NSEG; s++) {
            const int cnt = s_wcnt[2 * s] + s_wcnt[2 * s + 1];
            s_base[s] = acc; s_cnt[s] = cnt; acc += cnt;
        }
    }
    __syncthreads();

    // Fill compact table (masked slots of a segment are a prefix of i).
    if (tid < NSEG * SGRID) {
        const int s = tid >> 6;
        const int i = tid & 63;
        if (i < s_cnt[s]) {
            const int p = s_base[s] + i;
            if (p < TPAD) {                      // pos >= 192 dropped by reference
                const float v  = __fdiv_rn((float)i, s_scale[s]);
                const float fl = floorf(v);
                s_src[p] = min((int)fl + s_off[s], TPAD - 2);
                s_lam[p] = v - fl;
            }
        }
    }
    __syncthreads();

    const ulonglong4* __restrict__ xb =
        (const ulonglong4*)(x + (size_t)b * TPAD * CCH);
    ulonglong4* __restrict__ ob =
        (ulonglong4*)(out + (size_t)b * TPAD * CCH);

    // Stream 192 rows x 10 x 32B per batch with 256-bit accesses.
    for (int e = tid; e < ROWV8; e += 512) {
        const int row = e / NV8;
        const int q   = e - row * NV8;
        const int   src = s_src[row];
        const float lam = s_lam[row];
        ulonglong4 r = make_ulonglong4(0ull, 0ull, 0ull, 0ull);
        if (src >= 0) {
            const ulonglong4 a = ldg256_evict_last(&xb[src * NV8 + q]);
            const ulonglong4 c = ldg256_evict_last(&xb[src * NV8 + NV8 + q]);
            r.x = lerp64(a.x, c.x, lam);
            r.y = lerp64(a.y, c.y, lam);
            r.z = lerp64(a.z, c.z, lam);
            r.w = lerp64(a.w, c.w, lam);
        }
        stg256_evict_first(&ob[e], r);
    }
}

extern "C" void kernel_launch(void* const* d_in, const int* in_sizes, int n_in,
                              void* d_out, int out_size)
{
    const float* x           = (const float*)d_in[0];
    const int*   len_seq     = (const int*)  d_in[1];
    const float* scales      = (const float*)d_in[2];
    const int*   len_seg_raw = (const int*)  d_in[3];
    float*       out         = (float*)d_out;

    const int B = in_sizes[1];
    interp_lnr_kernel<<<B, 512>>>(x, len_seq, scales, len_seg_raw, out);
}